// round 14
// baseline (speedup 1.0000x reference)
#include <cuda_runtime.h>
#include <cuda_bf16.h>

// src [8,16,512,512] f32, flow [8,2,512,512] f32, out [8,16,512,512] f32.
//
// Index math reproduces XLA's lowering bit-exactly (reciprocal-constant rewrite
// of /511, fp32-rounded intermediates, no FMA contraction, rint half-to-even,
// border clamp). Verified rel_err == 0.0 in R3-R13.
//
// R14 = R13 with the final locality doubling: 32(x) x 32(h) tile, 1024 threads,
// 1 px/thread. Vertical gather overfetch 1.5x -> 1.25x, and the per-CTA L1
// gather footprint (16ch x ~6.4KB x 2 CTAs ~ 205KB) now FITS in the 228KB L1
// (at 32x16 it was ~244KB and thrashed). Occupancy held at 64 warps/SM.

#define B 8
#define C 16
#define H 512
#define W 512
#define HW (H * W)          // 1<<18
#define W_BITS 9

#define TILE_X 32           // lanes: consecutive x (coalesced)
#define TILE_H 32           // warps: consecutive rows (L1 line sharing)
#define TPB (TILE_X * TILE_H)   // 1024
#define XT (W / TILE_X)     // 16 x-tiles
#define HT (H / TILE_H)     // 16 h-tiles

__device__ __forceinline__ int ref_index(float coord, float disp)
{
    const float rcp = 1.0f / 511.0f;         // fp32(1/511), XLA recip rewrite
    float t = __fadd_rn(coord, disp);        // ii + flow
    t = __fmul_rn(t, rcp);                   // * (1/511)
    t = __fadd_rn(t, -0.5f);                 // - 0.5
    t = __fmul_rn(2.0f, t);                  // * 2 (exact)
    t = __fadd_rn(t, 1.0f);                  // + 1
    t = __fmul_rn(t, 0.5f);                  // * 0.5 (exact)
    t = __fmul_rn(t, 511.0f);                // * 511
    int i = __float2int_rn(t);               // round half-to-even
    return min(max(i, 0), 511);              // border clamp
}

__global__ __launch_bounds__(TPB, 2) void flow_warp_tile32_kernel(
    const float* __restrict__ src,
    const float* __restrict__ flow,
    float* __restrict__ out)
{
    int bidx = blockIdx.x;
    int xt = bidx & (XT - 1);               // x-tile
    int ht = (bidx >> 4) & (HT - 1);        // h-tile
    int b  = bidx >> 8;                     // batch (16*16 = 256 tiles/img)

    int lane = threadIdx.x & 31;
    int wrp  = threadIdx.x >> 5;            // 0..31 -> row within tile

    int h  = ht * TILE_H + wrp;
    int w  = xt * TILE_X + lane;
    int hw = (h << W_BITS) + w;

    const float* fb = flow + (size_t)b * 2 * HW;
    float f0 = __ldcs(fb + hw);             // row displacement (streamed)
    float f1 = __ldcs(fb + HW + hw);        // col displacement (streamed)

    int yi = ref_index((float)h, f0);
    int xi = ref_index((float)w, f1);
    int lin = (yi << W_BITS) + xi;

    const float* sb = src + (size_t)b * C * HW;
    float*       ob = out + (size_t)b * C * HW;

    #pragma unroll
    for (int c = 0; c < C; ++c) {
        __stcs(ob + c * HW + hw, __ldg(sb + c * HW + lin));
    }
}

extern "C" void kernel_launch(void* const* d_in, const int* in_sizes, int n_in,
                              void* d_out, int out_size)
{
    const float* src  = (const float*)d_in[0];
    const float* flow = (const float*)d_in[1];
    float*       out  = (float*)d_out;

    int blocks = B * HT * XT;              // 8 * 16 * 16 = 2048
    flow_warp_tile32_kernel<<<blocks, TPB>>>(src, flow, out);
}

// round 16
// speedup vs baseline: 1.0423x; 1.0423x over previous
#include <cuda_runtime.h>
#include <cuda_bf16.h>

// src [8,16,512,512] f32, flow [8,2,512,512] f32, out [8,16,512,512] f32.
//
// Index math reproduces XLA's lowering bit-exactly (reciprocal-constant rewrite
// of /511, fp32-rounded intermediates, no FMA contraction, rint half-to-even,
// border clamp). Verified rel_err == 0.0 in R3-R14.
//
// R16 = R13 (best: 32x16 tile, 512 thr, 1 px/thread, 64 warps/SM) with the
// L2 retention lever expressed legally for sm_103a:
//   createpolicy.fractional.L2::evict_last  +  ld.global.nc.L2::cache_hint
// (the direct .L2::evict_last modifier is vector-only on this ptxas).
// Goal: pin the ~128MB src in the 126MB L2 across graph replays; stores stay
// evict-first (__stcs) so write-allocates don't evict src; flow streamed.

#define B 8
#define C 16
#define H 512
#define W 512
#define HW (H * W)          // 1<<18
#define W_BITS 9

#define TILE_X 32           // lanes: consecutive x (coalesced)
#define TILE_H 16           // warps: consecutive rows (L1 line sharing)
#define TPB (TILE_X * TILE_H)   // 512
#define XT (W / TILE_X)     // 16 x-tiles
#define HT (H / TILE_H)     // 32 h-tiles

__device__ __forceinline__ int ref_index(float coord, float disp)
{
    const float rcp = 1.0f / 511.0f;         // fp32(1/511), XLA recip rewrite
    float t = __fadd_rn(coord, disp);        // ii + flow
    t = __fmul_rn(t, rcp);                   // * (1/511)
    t = __fadd_rn(t, -0.5f);                 // - 0.5
    t = __fmul_rn(2.0f, t);                  // * 2 (exact)
    t = __fadd_rn(t, 1.0f);                  // + 1
    t = __fmul_rn(t, 0.5f);                  // * 0.5 (exact)
    t = __fmul_rn(t, 511.0f);                // * 511
    int i = __float2int_rn(t);               // round half-to-even
    return min(max(i, 0), 511);              // border clamp
}

// Gather load carrying an L2 evict_last cache-hint policy.
__device__ __forceinline__ float ldg_keep(const float* p, unsigned long long pol)
{
    float v;
    asm("ld.global.nc.L2::cache_hint.f32 %0, [%1], %2;"
        : "=f"(v) : "l"(p), "l"(pol));
    return v;
}

__global__ __launch_bounds__(TPB, 4) void flow_warp_tile16_keep_kernel(
    const float* __restrict__ src,
    const float* __restrict__ flow,
    float* __restrict__ out)
{
    int bidx = blockIdx.x;
    int xt = bidx & (XT - 1);               // x-tile
    int ht = (bidx >> 4) & (HT - 1);        // h-tile
    int b  = bidx >> 9;                     // batch (16*32 = 512 tiles/img)

    int lane = threadIdx.x & 31;
    int wrp  = threadIdx.x >> 5;            // 0..15 -> row within tile

    int h  = ht * TILE_H + wrp;
    int w  = xt * TILE_X + lane;
    int hw = (h << W_BITS) + w;

    // Fully-evict_last fractional policy (uniform; cheap UDP op).
    unsigned long long pol;
    asm("createpolicy.fractional.L2::evict_last.b64 %0, 1.0;" : "=l"(pol));

    const float* fb = flow + (size_t)b * 2 * HW;
    float f0 = __ldcs(fb + hw);             // row displacement (streamed)
    float f1 = __ldcs(fb + HW + hw);        // col displacement (streamed)

    int yi = ref_index((float)h, f0);
    int xi = ref_index((float)w, f1);
    int lin = (yi << W_BITS) + xi;

    const float* sb = src + (size_t)b * C * HW;
    float*       ob = out + (size_t)b * C * HW;

    #pragma unroll
    for (int c = 0; c < C; ++c) {
        __stcs(ob + c * HW + hw, ldg_keep(sb + c * HW + lin, pol));
    }
}

extern "C" void kernel_launch(void* const* d_in, const int* in_sizes, int n_in,
                              void* d_out, int out_size)
{
    const float* src  = (const float*)d_in[0];
    const float* flow = (const float*)d_in[1];
    float*       out  = (float*)d_out;

    int blocks = B * HT * XT;              // 8 * 32 * 16 = 4096
    flow_warp_tile16_keep_kernel<<<blocks, TPB>>>(src, flow, out);
}